// round 7
// baseline (speedup 1.0000x reference)
#include <cuda_runtime.h>

#define cB 2
#define cN 2048
#define cDIM 1024
#define cH 16
#define cD 64
#define cE 3072      // 3*DIM
#define cM 4096      // B*N
#define cK 1024

// Scratch: q,k,v in [B,H,N,D] layout (16 MB each)
__device__ float g_q[cB * cH * cN * cD];
__device__ float g_k[cB * cH * cN * cD];
__device__ float g_v[cB * cH * cN * cD];

// ---- packed f32x2 helpers (sm_103a FFMA2 path) -----------------------------
typedef unsigned long long u64;

__device__ __forceinline__ u64 pk2(float lo, float hi) {
    u64 r;
    asm("mov.b64 %0, {%1, %2};" : "=l"(r) : "f"(lo), "f"(hi));
    return r;
}
__device__ __forceinline__ void upk2(float& lo, float& hi, u64 v) {
    asm("mov.b64 {%0, %1}, %2;" : "=f"(lo), "=f"(hi) : "l"(v));
}
__device__ __forceinline__ void fma2(u64& d, u64 a, u64 b) {
    asm("fma.rn.f32x2 %0, %1, %2, %0;" : "+l"(d) : "l"(a), "l"(b));
}

// ---------------------------------------------------------------------------
// Kernel 1: qkv = x @ W^T + b, scattered into g_q/g_k/g_v as [B,H,N,D].
// 128x128 tile, BK=16, 256 threads, 8x8/thread, double-buffered smem,
// inner product in packed f32x2 (rows paired): 32 FFMA2 + 12 packs per k.
// ---------------------------------------------------------------------------
__global__ __launch_bounds__(256, 2) void qkv_gemm(const float* __restrict__ x,
                                                   const float* __restrict__ w,
                                                   const float* __restrict__ bias) {
    __shared__ float As[2][16][128];
    __shared__ float Bs[2][16][128];
    const int tid = threadIdx.x;
    const int tx = tid & 15;
    const int ty = tid >> 4;
    const int m0 = blockIdx.y * 128;
    const int e0 = blockIdx.x * 128;

    const int row0 = tid >> 2;                // 0..63
    const int c0   = (tid & 3) * 4;
    const int row1 = (tid + 256) >> 2;        // 64..127
    const int c1   = ((tid + 256) & 3) * 4;

    const float* xa0 = x + (size_t)(m0 + row0) * cK + c0;
    const float* xa1 = x + (size_t)(m0 + row1) * cK + c1;
    const float* wb0 = w + (size_t)(e0 + row0) * cK + c0;
    const float* wb1 = w + (size_t)(e0 + row1) * cK + c1;

    // Packed accumulators: accp[i2][j] holds rows (2*i2, 2*i2+1) x col j
    u64 accp[4][8];
#pragma unroll
    for (int i = 0; i < 4; i++)
#pragma unroll
        for (int j = 0; j < 8; j++) accp[i][j] = 0ull;

    float4 pa0 = *(const float4*)(xa0);
    float4 pa1 = *(const float4*)(xa1);
    float4 pb0 = *(const float4*)(wb0);
    float4 pb1 = *(const float4*)(wb1);

    int buf = 0;
    for (int kt = 0; kt < 64; kt++) {
        As[buf][c0 + 0][row0] = pa0.x;
        As[buf][c0 + 1][row0] = pa0.y;
        As[buf][c0 + 2][row0] = pa0.z;
        As[buf][c0 + 3][row0] = pa0.w;
        As[buf][c1 + 0][row1] = pa1.x;
        As[buf][c1 + 1][row1] = pa1.y;
        As[buf][c1 + 2][row1] = pa1.z;
        As[buf][c1 + 3][row1] = pa1.w;
        Bs[buf][c0 + 0][row0] = pb0.x;
        Bs[buf][c0 + 1][row0] = pb0.y;
        Bs[buf][c0 + 2][row0] = pb0.z;
        Bs[buf][c0 + 3][row0] = pb0.w;
        Bs[buf][c1 + 0][row1] = pb1.x;
        Bs[buf][c1 + 1][row1] = pb1.y;
        Bs[buf][c1 + 2][row1] = pb1.z;
        Bs[buf][c1 + 3][row1] = pb1.w;
        __syncthreads();

        if (kt < 63) {
            int off = (kt + 1) * 16;
            pa0 = *(const float4*)(xa0 + off);
            pa1 = *(const float4*)(xa1 + off);
            pb0 = *(const float4*)(wb0 + off);
            pb1 = *(const float4*)(wb1 + off);
        }

#pragma unroll
        for (int k = 0; k < 16; k++) {
            float a[8], b[8];
            *(float4*)&a[0] = *(const float4*)&As[buf][k][ty * 4];
            *(float4*)&a[4] = *(const float4*)&As[buf][k][64 + ty * 4];
            *(float4*)&b[0] = *(const float4*)&Bs[buf][k][tx * 4];
            *(float4*)&b[4] = *(const float4*)&Bs[buf][k][64 + tx * 4];
            u64 ap[4];
            ap[0] = pk2(a[0], a[1]);
            ap[1] = pk2(a[2], a[3]);
            ap[2] = pk2(a[4], a[5]);
            ap[3] = pk2(a[6], a[7]);
#pragma unroll
            for (int j = 0; j < 8; j++) {
                u64 bd = pk2(b[j], b[j]);
#pragma unroll
                for (int i2 = 0; i2 < 4; i2++)
                    fma2(accp[i2][j], ap[i2], bd);
            }
        }
        buf ^= 1;
    }

    // Unpack and scatter epilogue
    float acc[8][8];
#pragma unroll
    for (int i2 = 0; i2 < 4; i2++)
#pragma unroll
        for (int j = 0; j < 8; j++)
            upk2(acc[2 * i2][j], acc[2 * i2 + 1][j], accp[i2][j]);

#pragma unroll
    for (int i = 0; i < 8; i++) {
        int m  = m0 + ((i < 4) ? (ty * 4 + i) : (64 + ty * 4 + i - 4));
        int bb = m >> 11;          // m / N
        int n  = m & (cN - 1);
#pragma unroll
        for (int j = 0; j < 8; j++) {
            int e = e0 + ((j < 4) ? (tx * 4 + j) : (64 + tx * 4 + j - 4));
            float v = acc[i][j] + __ldg(bias + e);
            int h   = e / 192;
            int rem = e - h * 192;
            int d   = rem / 3;
            int jj  = rem - d * 3;
            size_t idx = ((size_t)(bb * cH + h) * cN + n) * cD + d;
            if (jj == 0)      g_q[idx] = v;
            else if (jj == 1) g_k[idx] = v;
            else              g_v[idx] = v;
        }
    }
}

// ---------------------------------------------------------------------------
// Kernel 2: in-place RMS-norm over head dim for q (blockIdx.y=0) and k (=1).
// ---------------------------------------------------------------------------
__global__ __launch_bounds__(256) void rmsnorm(const float* __restrict__ qw,
                                               const float* __restrict__ kw) {
    int warp = threadIdx.x >> 5;
    int lane = threadIdx.x & 31;
    size_t row = (size_t)blockIdx.x * 8 + warp;     // < B*H*N = 65536
    float* base = blockIdx.y ? g_k : g_q;
    const float* wv = blockIdx.y ? kw : qw;

    float2 v = *(float2*)(base + row * cD + lane * 2);
    float ss = v.x * v.x + v.y * v.y;
#pragma unroll
    for (int o = 16; o > 0; o >>= 1) ss += __shfl_xor_sync(0xffffffffu, ss, o);
    float inv = rsqrtf(ss * (1.0f / cD) + 1e-6f);
    float2 g = *(const float2*)(wv + lane * 2);
    v.x *= inv * g.x;
    v.y *= inv * g.y;
    *(float2*)(base + row * cD + lane * 2) = v;
}

// ---------------------------------------------------------------------------
// Kernel 3: attention, flash-style WITHOUT online max (|score| <= 8 exactly:
// RMS norm fixes ||q||=||k||=8, scale=0.125). 128-row Q tile, 64-key tiles,
// 256 threads, 8x4 per thread with packed-f32x2 math (rows paired).
// Smem (dynamic, 96KB): Qs[128][64], Ks[64][64] ([d][c]), Vs[64][64],
// Ps[128][64]. 3 syncs per key tile.
// ---------------------------------------------------------------------------
__global__ __launch_bounds__(256, 2) void attn(float* __restrict__ out) {
    extern __shared__ float sm[];
    float* Qs = sm;                 // [128][64]
    float* Ks = sm + 8192;          // [64][64]  (K transposed: [d][c])
    float* Vs = sm + 12288;         // [64][64]  ([c][d])
    float* Ps = sm + 16384;         // [128][64]

    const int tid = threadIdx.x;
    const int tx = tid & 15;
    const int ty = tid >> 4;
    const int bh = blockIdx.y;             // 0..31  (b*H + h)
    const int q0 = blockIdx.x * 128;
    const float* qb = g_q + (size_t)bh * cN * cD;
    const float* kb = g_k + (size_t)bh * cN * cD;
    const float* vb = g_v + (size_t)bh * cN * cD;

#pragma unroll
    for (int p = 0; p < 8; p++) {
        int l  = tid + p * 256;
        int r  = l >> 4;
        int c4 = (l & 15) * 4;
        *(float4*)&Qs[r * 64 + c4] = *(const float4*)(qb + (size_t)(q0 + r) * cD + c4);
    }

    // op[i2][j]: packed rows (2*i2, 2*i2+1), col j
    u64 op[4][4];
    float lsum[8];
#pragma unroll
    for (int i = 0; i < 4; i++)
#pragma unroll
        for (int j = 0; j < 4; j++) op[i][j] = 0ull;
#pragma unroll
    for (int i = 0; i < 8; i++) lsum[i] = 0.f;

    for (int kt = 0; kt < cN; kt += 64) {
        __syncthreads();   // prev-iter Ps/Vs readers done (covers Q load iter 0)

        // K tile transposed: Ks[d][c] = k[kt+c][d]
#pragma unroll
        for (int p = 0; p < 4; p++) {
            int l  = tid + p * 256;
            int c  = l & 63;
            int d4 = (l >> 6) * 4;
            float4 t = *(const float4*)(kb + (size_t)(kt + c) * cD + d4);
            Ks[(d4 + 0) * 64 + c] = t.x;
            Ks[(d4 + 1) * 64 + c] = t.y;
            Ks[(d4 + 2) * 64 + c] = t.z;
            Ks[(d4 + 3) * 64 + c] = t.w;
        }
        // V tile row-major: Vs[c][d]
#pragma unroll
        for (int p = 0; p < 4; p++) {
            int l  = tid + p * 256;
            int r  = l >> 4;
            int c4 = (l & 15) * 4;
            *(float4*)&Vs[r * 64 + c4] = *(const float4*)(vb + (size_t)(kt + r) * cD + c4);
        }
        __syncthreads();

        // S = Q K^T (packed f32x2, rows paired)
        u64 sp[4][4];
#pragma unroll
        for (int i = 0; i < 4; i++)
#pragma unroll
            for (int j = 0; j < 4; j++) sp[i][j] = 0ull;

#pragma unroll
        for (int d4 = 0; d4 < 64; d4 += 4) {
            float4 q4[8];
#pragma unroll
            for (int i = 0; i < 8; i++)
                q4[i] = *(const float4*)&Qs[(ty * 8 + i) * 64 + d4];
#pragma unroll
            for (int dd = 0; dd < 4; dd++) {
                float4 kv = *(const float4*)&Ks[(d4 + dd) * 64 + tx * 4];
                u64 bd0 = pk2(kv.x, kv.x);
                u64 bd1 = pk2(kv.y, kv.y);
                u64 bd2 = pk2(kv.z, kv.z);
                u64 bd3 = pk2(kv.w, kv.w);
#pragma unroll
                for (int i2 = 0; i2 < 4; i2++) {
                    const float* qlo = (const float*)&q4[2 * i2];
                    const float* qhi = (const float*)&q4[2 * i2 + 1];
                    u64 ap = pk2(qlo[dd], qhi[dd]);
                    fma2(sp[i2][0], ap, bd0);
                    fma2(sp[i2][1], ap, bd1);
                    fma2(sp[i2][2], ap, bd2);
                    fma2(sp[i2][3], ap, bd3);
                }
            }
        }

        // P = exp(S * scale); row sums; stage P
#pragma unroll
        for (int i2 = 0; i2 < 4; i2++) {
            float slo[4], shi[4];
#pragma unroll
            for (int j = 0; j < 4; j++) upk2(slo[j], shi[j], sp[i2][j]);
            float4 plo, phi;
            plo.x = __expf(slo[0] * 0.125f);
            plo.y = __expf(slo[1] * 0.125f);
            plo.z = __expf(slo[2] * 0.125f);
            plo.w = __expf(slo[3] * 0.125f);
            phi.x = __expf(shi[0] * 0.125f);
            phi.y = __expf(shi[1] * 0.125f);
            phi.z = __expf(shi[2] * 0.125f);
            phi.w = __expf(shi[3] * 0.125f);
            lsum[2 * i2]     += plo.x + plo.y + plo.z + plo.w;
            lsum[2 * i2 + 1] += phi.x + phi.y + phi.z + phi.w;
            *(float4*)&Ps[(ty * 8 + 2 * i2) * 64 + tx * 4]     = plo;
            *(float4*)&Ps[(ty * 8 + 2 * i2 + 1) * 64 + tx * 4] = phi;
        }
        __syncthreads();

        // O += P * V (packed)
#pragma unroll
        for (int c4 = 0; c4 < 64; c4 += 4) {
            float4 p4[8];
#pragma unroll
            for (int i = 0; i < 8; i++)
                p4[i] = *(const float4*)&Ps[(ty * 8 + i) * 64 + c4];
#pragma unroll
            for (int cc = 0; cc < 4; cc++) {
                float4 vv = *(const float4*)&Vs[(c4 + cc) * 64 + tx * 4];
                u64 bd0 = pk2(vv.x, vv.x);
                u64 bd1 = pk2(vv.y, vv.y);
                u64 bd2 = pk2(vv.z, vv.z);
                u64 bd3 = pk2(vv.w, vv.w);
#pragma unroll
                for (int i2 = 0; i2 < 4; i2++) {
                    const float* plo = (const float*)&p4[2 * i2];
                    const float* phi = (const float*)&p4[2 * i2 + 1];
                    u64 ap = pk2(plo[cc], phi[cc]);
                    fma2(op[i2][0], ap, bd0);
                    fma2(op[i2][1], ap, bd1);
                    fma2(op[i2][2], ap, bd2);
                    fma2(op[i2][3], ap, bd3);
                }
            }
        }
    }

    // Reduce row sums across the 16 tx lanes
#pragma unroll
    for (int i = 0; i < 8; i++) {
#pragma unroll
        for (int off = 1; off < 16; off <<= 1)
            lsum[i] += __shfl_xor_sync(0xffffffffu, lsum[i], off);
    }

    // Write out: out[b][n][h*64 + d]
    int bb = bh >> 4;
    int h  = bh & 15;
#pragma unroll
    for (int i2 = 0; i2 < 4; i2++) {
        float olo[4], ohi[4];
#pragma unroll
        for (int j = 0; j < 4; j++) upk2(olo[j], ohi[j], op[i2][j]);
        int nlo = q0 + ty * 8 + 2 * i2;
        int nhi = nlo + 1;
        float ilo = 1.0f / lsum[2 * i2];
        float ihi = 1.0f / lsum[2 * i2 + 1];
        float4 r4;
        r4.x = olo[0] * ilo; r4.y = olo[1] * ilo;
        r4.z = olo[2] * ilo; r4.w = olo[3] * ilo;
        *(float4*)(out + ((size_t)(bb * cN + nlo)) * cDIM + h * cD + tx * 4) = r4;
        r4.x = ohi[0] * ihi; r4.y = ohi[1] * ihi;
        r4.z = ohi[2] * ihi; r4.w = ohi[3] * ihi;
        *(float4*)(out + ((size_t)(bb * cN + nhi)) * cDIM + h * cD + tx * 4) = r4;
    }
}

// ---------------------------------------------------------------------------
extern "C" void kernel_launch(void* const* d_in, const int* in_sizes, int n_in,
                              void* d_out, int out_size) {
    const float* x        = (const float*)d_in[0];
    const float* qkv_w    = (const float*)d_in[1];
    const float* qkv_b    = (const float*)d_in[2];
    const float* q_norm_w = (const float*)d_in[3];
    const float* k_norm_w = (const float*)d_in[4];
    float* out = (float*)d_out;

    // Idempotent, not a stream op (graph-capture safe); no static guard.
    cudaFuncSetAttribute(attn, cudaFuncAttributeMaxDynamicSharedMemorySize,
                         96 * 1024);

    dim3 g1(cE / 128, cM / 128);         // 24 x 32
    qkv_gemm<<<g1, 256>>>(x, qkv_w, qkv_b);

    dim3 g2((cB * cH * cN) / 8, 2);      // 8192 x 2
    rmsnorm<<<g2, 256>>>(q_norm_w, k_norm_w);

    dim3 g3(cN / 128, cB * cH);          // 16 x 32
    attn<<<g3, 256, 96 * 1024>>>(out);
}

// round 8
// speedup vs baseline: 1.0175x; 1.0175x over previous
#include <cuda_runtime.h>

#define cB 2
#define cN 2048
#define cDIM 1024
#define cH 16
#define cD 64
#define cE 3072      // 3*DIM
#define cM 4096      // B*N
#define cK 1024

// Scratch: q,k,v in [B,H,N,D] layout (16 MB each)
__device__ float g_q[cB * cH * cN * cD];
__device__ float g_k[cB * cH * cN * cD];
__device__ float g_v[cB * cH * cN * cD];

// ---- tf32 helpers ----------------------------------------------------------
__device__ __forceinline__ unsigned f2tf32(float x) {
    unsigned r;
    asm("cvt.rna.tf32.f32 %0, %1;" : "=r"(r) : "f"(x));
    return r;
}
// D += A * B  (m16n8k8 tf32)
__device__ __forceinline__ void mma_tf32(float* cc, const unsigned* a,
                                         unsigned b0, unsigned b1) {
    asm volatile(
        "mma.sync.aligned.m16n8k8.row.col.f32.tf32.tf32.f32 "
        "{%0,%1,%2,%3}, {%4,%5,%6,%7}, {%8,%9}, {%0,%1,%2,%3};"
        : "+f"(cc[0]), "+f"(cc[1]), "+f"(cc[2]), "+f"(cc[3])
        : "r"(a[0]), "r"(a[1]), "r"(a[2]), "r"(a[3]), "r"(b0), "r"(b1));
}

// ---------------------------------------------------------------------------
// Kernel 1: qkv = x @ W^T + b via split-tf32 tensor-core mma.
// CTA tile 128x128, BK=32, 256 threads = 8 warps (4 in M x 2 in N),
// warp tile 32x64 = 2 m-tiles x 8 n-tiles of m16n8k8.
// Split precision: x = hi + lo (both tf32); D += Ahi*Bhi + Ahi*Blo + Alo*Bhi
// -> ~2^-22 relative error (fp32-class).
// Smem: Ahi/Alo/Bhi/Blo each [32][132] (k-major, padded) = 66 KB dynamic.
// ---------------------------------------------------------------------------
#define GP 132   // padded row length

__global__ __launch_bounds__(256) void qkv_gemm(const float* __restrict__ x,
                                                const float* __restrict__ w,
                                                const float* __restrict__ bias) {
    extern __shared__ float smg[];
    float* Ahi = smg;                  // [32][GP]
    float* Alo = smg + 32 * GP;
    float* Bhi = smg + 64 * GP;
    float* Blo = smg + 96 * GP;

    const int tid  = threadIdx.x;
    const int lane = tid & 31;
    const int wid  = tid >> 5;
    const int wm   = wid & 3;          // 0..3 (M)
    const int wn   = wid >> 2;         // 0..1 (N)
    const int g    = lane >> 2;        // 0..7
    const int c    = lane & 3;         // 0..3
    const int m0   = blockIdx.y * 128;
    const int e0   = blockIdx.x * 128;

    float acc[2][8][4];
#pragma unroll
    for (int mt = 0; mt < 2; mt++)
#pragma unroll
        for (int nt = 0; nt < 8; nt++)
#pragma unroll
            for (int i = 0; i < 4; i++) acc[mt][nt][i] = 0.f;

    for (int kt = 0; kt < cK; kt += 32) {
        __syncthreads();   // previous-iter readers done
        // Load + split-convert the 128x32 A and B tiles into k-major smem.
#pragma unroll
        for (int p = 0; p < 4; p++) {
            int l   = tid + p * 256;
            int row = l >> 3;              // 0..127
            int c4  = (l & 7) * 4;         // 0,4,...,28
            float4 av = *(const float4*)(x + (size_t)(m0 + row) * cK + kt + c4);
            float4 bv = *(const float4*)(w + (size_t)(e0 + row) * cK + kt + c4);
            float va[4] = {av.x, av.y, av.z, av.w};
            float vb[4] = {bv.x, bv.y, bv.z, bv.w};
#pragma unroll
            for (int i = 0; i < 4; i++) {
                unsigned hb = f2tf32(va[i]);
                float    hf = __uint_as_float(hb);
                unsigned lb = f2tf32(va[i] - hf);
                Ahi[(c4 + i) * GP + row] = __uint_as_float(hb);
                Alo[(c4 + i) * GP + row] = __uint_as_float(lb);
                hb = f2tf32(vb[i]);
                hf = __uint_as_float(hb);
                lb = f2tf32(vb[i] - hf);
                Bhi[(c4 + i) * GP + row] = __uint_as_float(hb);
                Blo[(c4 + i) * GP + row] = __uint_as_float(lb);
            }
        }
        __syncthreads();

#pragma unroll
        for (int kc = 0; kc < 4; kc++) {
            const int kb = kc * 8;
            // A fragments (2 m-tiles), hi and lo
            unsigned ah[2][4], al[2][4];
#pragma unroll
            for (int mt = 0; mt < 2; mt++) {
                int r = wm * 32 + mt * 16 + g;
                ah[mt][0] = __float_as_uint(Ahi[(kb + c) * GP + r]);
                ah[mt][1] = __float_as_uint(Ahi[(kb + c) * GP + r + 8]);
                ah[mt][2] = __float_as_uint(Ahi[(kb + c + 4) * GP + r]);
                ah[mt][3] = __float_as_uint(Ahi[(kb + c + 4) * GP + r + 8]);
                al[mt][0] = __float_as_uint(Alo[(kb + c) * GP + r]);
                al[mt][1] = __float_as_uint(Alo[(kb + c) * GP + r + 8]);
                al[mt][2] = __float_as_uint(Alo[(kb + c + 4) * GP + r]);
                al[mt][3] = __float_as_uint(Alo[(kb + c + 4) * GP + r + 8]);
            }
#pragma unroll
            for (int nt = 0; nt < 8; nt++) {
                int nn = wn * 64 + nt * 8 + g;
                unsigned bh0 = __float_as_uint(Bhi[(kb + c) * GP + nn]);
                unsigned bh1 = __float_as_uint(Bhi[(kb + c + 4) * GP + nn]);
                unsigned bl0 = __float_as_uint(Blo[(kb + c) * GP + nn]);
                unsigned bl1 = __float_as_uint(Blo[(kb + c + 4) * GP + nn]);
#pragma unroll
                for (int mt = 0; mt < 2; mt++) {
                    mma_tf32(acc[mt][nt], ah[mt], bh0, bh1);
                    mma_tf32(acc[mt][nt], ah[mt], bl0, bl1);
                    mma_tf32(acc[mt][nt], al[mt], bh0, bh1);
                }
            }
        }
    }

    // Epilogue: bias + scatter into q/k/v [B,H,N,D].
    // c0=(g,2c) c1=(g,2c+1) c2=(g+8,2c) c3=(g+8,2c+1)
#pragma unroll
    for (int mt = 0; mt < 2; mt++) {
#pragma unroll
        for (int hr = 0; hr < 2; hr++) {
            int m  = m0 + wm * 32 + mt * 16 + g + hr * 8;
            int bb = m >> 11;
            int n  = m & (cN - 1);
#pragma unroll
            for (int nt = 0; nt < 8; nt++) {
#pragma unroll
                for (int cc = 0; cc < 2; cc++) {
                    int e = e0 + wn * 64 + nt * 8 + 2 * c + cc;
                    float v = acc[mt][nt][hr * 2 + cc] + __ldg(bias + e);
                    int h   = e / 192;
                    int rem = e - h * 192;
                    int d   = rem / 3;
                    int jj  = rem - d * 3;
                    size_t idx = ((size_t)(bb * cH + h) * cN + n) * cD + d;
                    if (jj == 0)      g_q[idx] = v;
                    else if (jj == 1) g_k[idx] = v;
                    else              g_v[idx] = v;
                }
            }
        }
    }
}

// ---------------------------------------------------------------------------
// Kernel 2: in-place RMS-norm over head dim for q (blockIdx.y=0) and k (=1).
// ---------------------------------------------------------------------------
__global__ __launch_bounds__(256) void rmsnorm(const float* __restrict__ qw,
                                               const float* __restrict__ kw) {
    int warp = threadIdx.x >> 5;
    int lane = threadIdx.x & 31;
    size_t row = (size_t)blockIdx.x * 8 + warp;     // < B*H*N = 65536
    float* base = blockIdx.y ? g_k : g_q;
    const float* wv = blockIdx.y ? kw : qw;

    float2 v = *(float2*)(base + row * cD + lane * 2);
    float ss = v.x * v.x + v.y * v.y;
#pragma unroll
    for (int o = 16; o > 0; o >>= 1) ss += __shfl_xor_sync(0xffffffffu, ss, o);
    float inv = rsqrtf(ss * (1.0f / cD) + 1e-6f);
    float2 g = *(const float2*)(wv + lane * 2);
    v.x *= inv * g.x;
    v.y *= inv * g.y;
    *(float2*)(base + row * cD + lane * 2) = v;
}

// ---------------------------------------------------------------------------
// Kernel 3: attention, flash-style WITHOUT online max (|score| <= 8 exactly:
// RMS norm fixes ||q||=||k||=8, scale=0.125). 128-row Q tile, 64-key tiles,
// 256 threads, 8x4 per thread, scalar FFMA (proven R4 version, ~855us).
// Smem (dynamic, 96KB): Qs[128][64], Ks[64][64] ([d][c]), Vs[64][64],
// Ps[128][64]. 3 syncs per key tile.
// ---------------------------------------------------------------------------
__global__ __launch_bounds__(256, 2) void attn(float* __restrict__ out) {
    extern __shared__ float sm[];
    float* Qs = sm;                 // [128][64]
    float* Ks = sm + 8192;          // [64][64]  (K transposed: [d][c])
    float* Vs = sm + 12288;         // [64][64]  ([c][d])
    float* Ps = sm + 16384;         // [128][64]

    const int tid = threadIdx.x;
    const int tx = tid & 15;
    const int ty = tid >> 4;
    const int bh = blockIdx.y;             // 0..31  (b*H + h)
    const int q0 = blockIdx.x * 128;
    const float* qb = g_q + (size_t)bh * cN * cD;
    const float* kb = g_k + (size_t)bh * cN * cD;
    const float* vb = g_v + (size_t)bh * cN * cD;

#pragma unroll
    for (int p = 0; p < 8; p++) {
        int l  = tid + p * 256;
        int r  = l >> 4;
        int c4 = (l & 15) * 4;
        *(float4*)&Qs[r * 64 + c4] = *(const float4*)(qb + (size_t)(q0 + r) * cD + c4);
    }

    float o[8][4];
    float lsum[8];
#pragma unroll
    for (int i = 0; i < 8; i++) {
        lsum[i] = 0.f;
#pragma unroll
        for (int j = 0; j < 4; j++) o[i][j] = 0.f;
    }

    for (int kt = 0; kt < cN; kt += 64) {
        __syncthreads();   // prev-iter Ps/Vs readers done (covers Q load iter 0)

        // K tile transposed: Ks[d][c] = k[kt+c][d]
#pragma unroll
        for (int p = 0; p < 4; p++) {
            int l  = tid + p * 256;
            int c  = l & 63;
            int d4 = (l >> 6) * 4;
            float4 t = *(const float4*)(kb + (size_t)(kt + c) * cD + d4);
            Ks[(d4 + 0) * 64 + c] = t.x;
            Ks[(d4 + 1) * 64 + c] = t.y;
            Ks[(d4 + 2) * 64 + c] = t.z;
            Ks[(d4 + 3) * 64 + c] = t.w;
        }
        // V tile row-major: Vs[c][d]
#pragma unroll
        for (int p = 0; p < 4; p++) {
            int l  = tid + p * 256;
            int r  = l >> 4;
            int c4 = (l & 15) * 4;
            *(float4*)&Vs[r * 64 + c4] = *(const float4*)(vb + (size_t)(kt + r) * cD + c4);
        }
        __syncthreads();

        // S = Q K^T  (8x4 per thread)
        float s[8][4];
#pragma unroll
        for (int i = 0; i < 8; i++)
#pragma unroll
            for (int j = 0; j < 4; j++) s[i][j] = 0.f;

#pragma unroll
        for (int d4 = 0; d4 < 64; d4 += 4) {
            float qf[8][4], kf[4][4];
#pragma unroll
            for (int i = 0; i < 8; i++) {
                float4 t = *(const float4*)&Qs[(ty * 8 + i) * 64 + d4];
                qf[i][0] = t.x; qf[i][1] = t.y; qf[i][2] = t.z; qf[i][3] = t.w;
            }
#pragma unroll
            for (int dd = 0; dd < 4; dd++) {
                float4 t = *(const float4*)&Ks[(d4 + dd) * 64 + tx * 4];
                kf[dd][0] = t.x; kf[dd][1] = t.y; kf[dd][2] = t.z; kf[dd][3] = t.w;
            }
#pragma unroll
            for (int i = 0; i < 8; i++)
#pragma unroll
                for (int j = 0; j < 4; j++)
#pragma unroll
                    for (int dd = 0; dd < 4; dd++)
                        s[i][j] += qf[i][dd] * kf[dd][j];
        }

        // P = exp(S * scale); row-sum partials; stage P in smem
#pragma unroll
        for (int i = 0; i < 8; i++) {
            float4 pv;
            pv.x = __expf(s[i][0] * 0.125f);
            pv.y = __expf(s[i][1] * 0.125f);
            pv.z = __expf(s[i][2] * 0.125f);
            pv.w = __expf(s[i][3] * 0.125f);
            lsum[i] += pv.x + pv.y + pv.z + pv.w;
            *(float4*)&Ps[(ty * 8 + i) * 64 + tx * 4] = pv;
        }
        __syncthreads();

        // O += P * V
#pragma unroll
        for (int c4 = 0; c4 < 64; c4 += 4) {
            float pf[8][4], vf[4][4];
#pragma unroll
            for (int i = 0; i < 8; i++) {
                float4 t = *(const float4*)&Ps[(ty * 8 + i) * 64 + c4];
                pf[i][0] = t.x; pf[i][1] = t.y; pf[i][2] = t.z; pf[i][3] = t.w;
            }
#pragma unroll
            for (int cc = 0; cc < 4; cc++) {
                float4 t = *(const float4*)&Vs[(c4 + cc) * 64 + tx * 4];
                vf[cc][0] = t.x; vf[cc][1] = t.y; vf[cc][2] = t.z; vf[cc][3] = t.w;
            }
#pragma unroll
            for (int i = 0; i < 8; i++)
#pragma unroll
                for (int j = 0; j < 4; j++)
#pragma unroll
                    for (int cc = 0; cc < 4; cc++)
                        o[i][j] += pf[i][cc] * vf[cc][j];
        }
    }

    // Reduce row sums across the 16 tx lanes
#pragma unroll
    for (int i = 0; i < 8; i++) {
#pragma unroll
        for (int off = 1; off < 16; off <<= 1)
            lsum[i] += __shfl_xor_sync(0xffffffffu, lsum[i], off);
    }

    // Write out: out[b][n][h*64 + d]
    int bb = bh >> 4;
    int h  = bh & 15;
#pragma unroll
    for (int i = 0; i < 8; i++) {
        int n = q0 + ty * 8 + i;
        float inv = 1.0f / lsum[i];
        float4 r4;
        r4.x = o[i][0] * inv;
        r4.y = o[i][1] * inv;
        r4.z = o[i][2] * inv;
        r4.w = o[i][3] * inv;
        *(float4*)(out + ((size_t)(bb * cN + n)) * cDIM + h * cD + tx * 4) = r4;
    }
}

// ---------------------------------------------------------------------------
extern "C" void kernel_launch(void* const* d_in, const int* in_sizes, int n_in,
                              void* d_out, int out_size) {
    const float* x        = (const float*)d_in[0];
    const float* qkv_w    = (const float*)d_in[1];
    const float* qkv_b    = (const float*)d_in[2];
    const float* q_norm_w = (const float*)d_in[3];
    const float* k_norm_w = (const float*)d_in[4];
    float* out = (float*)d_out;

    const int gemm_smem = 128 * GP * (int)sizeof(float);   // 67,584 B

    // Idempotent, not stream ops (graph-capture safe); no static guards.
    cudaFuncSetAttribute(qkv_gemm, cudaFuncAttributeMaxDynamicSharedMemorySize,
                         gemm_smem);
    cudaFuncSetAttribute(attn, cudaFuncAttributeMaxDynamicSharedMemorySize,
                         96 * 1024);

    dim3 g1(cE / 128, cM / 128);         // 24 x 32
    qkv_gemm<<<g1, 256, gemm_smem>>>(x, qkv_w, qkv_b);

    dim3 g2((cB * cH * cN) / 8, 2);      // 8192 x 2
    rmsnorm<<<g2, 256>>>(q_norm_w, k_norm_w);

    dim3 g3(cN / 128, cB * cH);          // 16 x 32
    attn<<<g3, 256, 96 * 1024>>>(out);
}